// round 5
// baseline (speedup 1.0000x reference)
#include <cuda_runtime.h>

// out[i,m,l] = w1[i,0]*t4[i,(m-1)%56,l] + w1[i,1]*t4[i,(m-2)%56,l]
// t4[i,n,l]  = sum_{j,k} x[j,n,l+k-1] * w2[i,j,k]   (zero-padded 3-tap)
//
// One block per (channel-half ihalf, output row m); 1024 threads.
// f32x2 lanes carry the two needed t4 rows (na=m-1, nb=m-2): x is stored
// row-interleaved in smem ({x[na],x[nb]} per LDS.64) and weights duplicated
// {w,w}, so every FFMA2 operand is one LDS.64, zero pack MOVs.
// Thread layout: jq(4 j-quarters) x il(32 channels) x lg(8 column groups).
// 8 warps/SMSP for latency coverage; weight stride padded to 193 ull to
// avoid the 4-way bank conflict of stride 192.

using ull = unsigned long long;

__device__ __forceinline__ ull pack2(float lo, float hi) {
    ull r; asm("mov.b64 %0, {%1, %2};" : "=l"(r) : "f"(lo), "f"(hi)); return r;
}
__device__ __forceinline__ ull fma2(ull a, ull b, ull c) {
    ull d; asm("fma.rn.f32x2 %0, %1, %2, %3;" : "=l"(d) : "l"(a), "l"(b), "l"(c)); return d;
}
__device__ __forceinline__ ull add2(ull a, ull b) {
    ull d; asm("add.rn.f32x2 %0, %1, %2;" : "=l"(d) : "l"(a), "l"(b)); return d;
}
__device__ __forceinline__ void unpack2(ull p, float& lo, float& hi) {
    asm("mov.b64 {%0, %1}, %2;" : "=f"(lo), "=f"(hi) : "l"(p));
}

// smem arena (ull units):
//   xs2 : 64*58   row-interleaved x pairs      [0 .. 3712)
//   w2d : 32*193  duplicated weights, padded   [3712 .. 9888)
//   rbuf: overlays arena after the main loop: 1024*7 = 7168 ull
static constexpr int XS2_OFF = 0;
static constexpr int W2D_OFF = 64 * 58;                    // 3712
static constexpr int ARENA_ULL = W2D_OFF + 32 * 193;       // 9888
static constexpr int ARENA_BYTES = ARENA_ULL * 8;          // 79104

__global__ __launch_bounds__(1024, 1) void fused_kernel(
    const float* __restrict__ x,
    const float* __restrict__ w1,
    const float* __restrict__ w2,
    float* __restrict__ out) {

    extern __shared__ ull arena[];
    ull* xs2 = arena + XS2_OFF;
    ull* w2d = arena + W2D_OFF;

    const int m     = blockIdx.y;
    const int ihalf = blockIdx.x;
    const int ibase = ihalf * 32;
    const int na    = (m + 55) % 56;
    const int nb    = (m + 54) % 56;
    const int tid   = threadIdx.x;

    // Halo zeros at padded cols 0 and 57.
    if (tid < 128) {
        int j = tid >> 1;
        xs2[j * 58 + ((tid & 1) ? 57 : 0)] = 0ull;
    }

    // Load both x rows, interleaved: xs2[j*58+1+l] = {x[na,l], x[nb,l]}.
    if (tid < 896) {                        // 64 ch * 14 float4
        int j  = tid / 14;
        int c4 = tid % 14;
        float4 va = *reinterpret_cast<const float4*>(&x[(j * 56 + na) * 56 + c4 * 4]);
        float4 vb = *reinterpret_cast<const float4*>(&x[(j * 56 + nb) * 56 + c4 * 4]);
        ull* d = &xs2[j * 58 + 1 + c4 * 4];
        d[0] = pack2(va.x, vb.x);
        d[1] = pack2(va.y, vb.y);
        d[2] = pack2(va.z, vb.z);
        d[3] = pack2(va.w, vb.w);
    }

    // Duplicate-pack this half's weights: w2d[il*193 + jk] = {w,w}.
    for (int idx = tid; idx < 32 * 192; idx += 1024) {
        int il = idx / 192;
        int jk = idx % 192;
        float w = w2[(ibase + il) * 192 + jk];
        w2d[il * 193 + jk] = pack2(w, w);
    }
    __syncthreads();

    const int jq = tid >> 8;        // 0..3  : j-quarter
    const int r  = tid & 255;
    const int il = r >> 3;          // 0..31 : channel within half
    const int lg = r & 7;           // 0..7  : column group
    const int l0 = lg * 7;
    const int j0 = jq * 16;

    ull acc[7];
#pragma unroll
    for (int q = 0; q < 7; ++q) acc[q] = 0ull;

#pragma unroll 2
    for (int jj = 0; jj < 16; ++jj) {
        const int j = j0 + jj;
        const ull* xp = &xs2[j * 58 + l0];
        const ull* wp = &w2d[il * 193 + 3 * j];
        ull pa[9];
#pragma unroll
        for (int q = 0; q < 9; ++q) pa[q] = xp[q];   // LDS.64, pair-ready
        const ull wk0 = wp[0];
        const ull wk1 = wp[1];
        const ull wk2 = wp[2];
#pragma unroll
        for (int q = 0; q < 7; ++q)
            acc[q] = fma2(pa[q], wk0,
                     fma2(pa[q + 1], wk1,
                     fma2(pa[q + 2], wk2, acc[q])));
    }

    // 4-way jq reduction through smem (overlay arena), slot-parallel epilogue.
    __syncthreads();                 // all xs2/w2d reads complete before overlay
    ull* rbuf = arena;               // 1024*7 ull = 57344 B < arena
    {
        ull* dst = &rbuf[(jq * 256 + r) * 7];
#pragma unroll
        for (int q = 0; q < 7; ++q) dst[q] = acc[q];
    }
    __syncthreads();

    // Each jq quarter finalizes slots q = jq, jq+4 (disjoint, all warps busy).
    const int i   = ibase + il;
    const float w10 = w1[2 * i];
    const float w11 = w1[2 * i + 1];
    float* orow = &out[(i * 56 + m) * 56 + l0];
#pragma unroll
    for (int q = jq; q < 7; q += 4) {
        ull v = add2(add2(rbuf[(0 * 256 + r) * 7 + q], rbuf[(1 * 256 + r) * 7 + q]),
                     add2(rbuf[(2 * 256 + r) * 7 + q], rbuf[(3 * 256 + r) * 7 + q]));
        float a, b;
        unpack2(v, a, b);
        orow[q] = fmaf(w10, a, w11 * b);
    }
}

extern "C" void kernel_launch(void* const* d_in, const int* in_sizes, int n_in,
                              void* d_out, int out_size) {
    const float* x  = (const float*)d_in[0];   // (1,64,56,56)
    const float* w1 = (const float*)d_in[1];   // (64,2)
    const float* w2 = (const float*)d_in[2];   // (64,64,3)
    float* out = (float*)d_out;                // (1,64,56,56)

    cudaFuncSetAttribute(fused_kernel,
                         cudaFuncAttributeMaxDynamicSharedMemorySize,
                         ARENA_BYTES);

    dim3 grid(2, 56);
    fused_kernel<<<grid, 1024, ARENA_BYTES>>>(x, w1, w2, out);
}

// round 6
// speedup vs baseline: 1.1805x; 1.1805x over previous
#include <cuda_runtime.h>

// out[i,m,l] = w1[i,0]*t4[i,(m-1)%56,l] + w1[i,1]*t4[i,(m-2)%56,l]
// t4[i,n,l]  = sum_{j,k} x[j,n,l+k-1] * w2[i,j,k]   (zero-padded 3-tap)
//
// One block per (channel-half, output row m); 512 threads, ~128-reg budget.
// f32x2 lanes carry the two needed t4 rows (na,nb). Each thread owns FOUR
// output channels (C=4) so one batch of 9 x-loads feeds 84 FFMA2 —
// high per-warp MLP + ILP instead of relying on warp count.
// Thread layout: js(8 j-splits) x cg(8 channel-quads) x lg(8 col groups).

using ull = unsigned long long;

__device__ __forceinline__ ull pack2(float lo, float hi) {
    ull r; asm("mov.b64 %0, {%1, %2};" : "=l"(r) : "f"(lo), "f"(hi)); return r;
}
__device__ __forceinline__ ull fma2(ull a, ull b, ull c) {
    ull d; asm("fma.rn.f32x2 %0, %1, %2, %3;" : "=l"(d) : "l"(a), "l"(b), "l"(c)); return d;
}
__device__ __forceinline__ ull add2(ull a, ull b) {
    ull d; asm("add.rn.f32x2 %0, %1, %2;" : "=l"(d) : "l"(a), "l"(b)); return d;
}
__device__ __forceinline__ void unpack2(ull p, float& lo, float& hi) {
    asm("mov.b64 {%0, %1}, %2;" : "=f"(lo), "=f"(hi) : "l"(p));
}

// smem arena (ull units):
//   xs2 : 64*58  row-interleaved x pairs      [0 .. 3712)
//   w2d : 32*193 duplicated weights (padded)  [3712 .. 9888)
//   rbuf overlays arena after main loop: 4 * 1832 = 7328 ull (57KB)
static constexpr int W2D_OFF    = 64 * 58;               // 3712
static constexpr int ARENA_ULL  = W2D_OFF + 32 * 193;    // 9888
static constexpr int ARENA_BYTES = ARENA_ULL * 8;        // 79104
static constexpr int RROW = 1832;                        // per-js rbuf stride (32*57 pad)

__global__ __launch_bounds__(512, 1) void fused_kernel(
    const float* __restrict__ x,
    const float* __restrict__ w1,
    const float* __restrict__ w2,
    float* __restrict__ out) {

    extern __shared__ ull arena[];
    ull* xs2 = arena;
    ull* w2d = arena + W2D_OFF;

    const int m     = blockIdx.y;
    const int ihalf = blockIdx.x;
    const int ibase = ihalf * 32;
    const int na    = (m + 55) % 56;
    const int nb    = (m + 54) % 56;
    const int tid   = threadIdx.x;

    // Halo zeros at padded cols 0 and 57.
    if (tid < 128) {
        int j = tid >> 1;
        xs2[j * 58 + ((tid & 1) ? 57 : 0)] = 0ull;
    }

    // Load both x rows interleaved: xs2[j*58+1+l] = {x[na,l], x[nb,l]}.
    for (int idx = tid; idx < 896; idx += 512) {      // 64 ch * 14 float4
        int j  = idx / 14;
        int c4 = idx % 14;
        float4 va = *reinterpret_cast<const float4*>(&x[(j * 56 + na) * 56 + c4 * 4]);
        float4 vb = *reinterpret_cast<const float4*>(&x[(j * 56 + nb) * 56 + c4 * 4]);
        ull* d = &xs2[j * 58 + 1 + c4 * 4];
        d[0] = pack2(va.x, vb.x);
        d[1] = pack2(va.y, vb.y);
        d[2] = pack2(va.z, vb.z);
        d[3] = pack2(va.w, vb.w);
    }

    // Duplicate-pack this half's weights: w2d[il*193 + jk] = {w,w}.
    for (int idx = tid; idx < 32 * 192; idx += 512) {
        int il = idx / 192;
        int jk = idx % 192;
        float w = w2[(ibase + il) * 192 + jk];
        w2d[il * 193 + jk] = pack2(w, w);
    }
    __syncthreads();

    const int js  = tid >> 6;         // 0..7 : j-split (8 j's each)
    const int cg  = (tid >> 3) & 7;   // 0..7 : channel quad
    const int lg  = tid & 7;          // 0..7 : column group
    const int l0  = lg * 7;
    const int il0 = cg * 4;
    const int j0  = js * 8;

    ull acc[4][7];
#pragma unroll
    for (int c = 0; c < 4; ++c)
#pragma unroll
        for (int q = 0; q < 7; ++q) acc[c][q] = 0ull;

#pragma unroll
    for (int jj = 0; jj < 8; ++jj) {
        const int j = j0 + jj;
        const ull* xp = &xs2[j * 58 + l0];
        ull pa[9];
#pragma unroll
        for (int q = 0; q < 9; ++q) pa[q] = xp[q];    // batched LDS.64, MLP=9

#pragma unroll
        for (int c = 0; c < 4; ++c) {
            const ull* wp = &w2d[(il0 + c) * 193 + 3 * j];
            const ull wk0 = wp[0];
            const ull wk1 = wp[1];
            const ull wk2 = wp[2];
#pragma unroll
            for (int q = 0; q < 7; ++q)
                acc[c][q] = fma2(pa[q], wk0,
                            fma2(pa[q + 1], wk1,
                            fma2(pa[q + 2], wk2, acc[c][q])));
        }
    }

    // ---- js reduction: 8 -> 4 via smem, then 4-way in epilogue ----
    __syncthreads();                 // xs2/w2d reads done before overlay
    ull* rbuf = arena;               // 4 * RROW ull = 57KB, fits arena

    if (js >= 4) {                   // upper half writes its partials
#pragma unroll
        for (int c = 0; c < 4; ++c)
#pragma unroll
            for (int q = 0; q < 7; ++q)
                rbuf[(js - 4) * RROW + (il0 + c) * 57 + l0 + q] = acc[c][q];
    }
    __syncthreads();

    if (js < 4) {                    // lower half merges (RMW of own slots)
#pragma unroll
        for (int c = 0; c < 4; ++c)
#pragma unroll
            for (int q = 0; q < 7; ++q) {
                int a = js * RROW + (il0 + c) * 57 + l0 + q;
                rbuf[a] = add2(acc[c][q], rbuf[a]);
            }
    }
    __syncthreads();

    // Slot-parallel epilogue over all 512 threads: 1792 output pairs.
    for (int s = tid; s < 32 * 56; s += 512) {
        int il = s / 56;
        int l  = s % 56;
        int a  = il * 57 + l;
        ull v = add2(add2(rbuf[0 * RROW + a], rbuf[1 * RROW + a]),
                     add2(rbuf[2 * RROW + a], rbuf[3 * RROW + a]));
        float ta, tb;
        unpack2(v, ta, tb);
        int i = ibase + il;
        out[(i * 56 + m) * 56 + l] = fmaf(__ldg(&w1[2 * i]), ta,
                                          __ldg(&w1[2 * i + 1]) * tb);
    }
}

extern "C" void kernel_launch(void* const* d_in, const int* in_sizes, int n_in,
                              void* d_out, int out_size) {
    const float* x  = (const float*)d_in[0];   // (1,64,56,56)
    const float* w1 = (const float*)d_in[1];   // (64,2)
    const float* w2 = (const float*)d_in[2];   // (64,64,3)
    float* out = (float*)d_out;                // (1,64,56,56)

    cudaFuncSetAttribute(fused_kernel,
                         cudaFuncAttributeMaxDynamicSharedMemorySize,
                         ARENA_BYTES);

    dim3 grid(2, 56);
    fused_kernel<<<grid, 512, ARENA_BYTES>>>(x, w1, w2, out);
}